// round 8
// baseline (speedup 1.0000x reference)
#include <cuda_runtime.h>

#define EPSLN 1e-5f
#define RS 68   // smem row stride in floats (4g+t bank pattern -> conflict-free)

// Precomputed per launch (deterministic, graph-capturable)
// B fragment for m16n8k8.row.col: b0 = W[ks*8+t][nt*8+g], b1 = W[ks*8+t+4][nt*8+g]
__device__ __align__(16) uint2 g_Wfrag[8 * 8 * 32];
__device__ __align__(16) float g_ewproj[16];         // We_w @ attn_w[128:192]

__device__ __forceinline__ unsigned cvt_tf32(float x) {
    unsigned r; asm("cvt.rna.tf32.f32 %0, %1;" : "=r"(r) : "f"(x)); return r;
}

#define MMA_TF32(d, a, b)                                                          \
    asm volatile(                                                                  \
        "mma.sync.aligned.m16n8k8.row.col.f32.tf32.tf32.f32 "                      \
        "{%0,%1,%2,%3},{%4,%5,%6,%7},{%8,%9},{%0,%1,%2,%3};"                       \
        : "+f"(d[0]), "+f"(d[1]), "+f"(d[2]), "+f"(d[3])                           \
        : "r"(a[0]), "r"(a[1]), "r"(a[2]), "r"(a[3]), "r"(b[0]), "r"(b[1]))

// Named barrier over the 64 threads (2 warps) serving one batch
#define BARX(id) asm volatile("bar.sync %0, 64;" :: "r"(id) : "memory")

__global__ void prep_kernel(const float* __restrict__ Ww,
                            const float* __restrict__ Wew,
                            const float* __restrict__ attw) {
    int tid = threadIdx.x;  // 256
    if (tid < 16) {
        float se = 0.f;
#pragma unroll 8
        for (int o = 0; o < 64; ++o) se += Wew[tid * 64 + o] * attw[128 + o];
        g_ewproj[tid] = se;
    }
    for (int idx = tid; idx < 2048; idx += 256) {
        int lane = idx & 31;
        int nt   = (idx >> 5) & 7;
        int ks   = idx >> 8;
        int t = lane & 3, g = lane >> 2;
        uint2 v;
        v.x = cvt_tf32(Ww[(ks * 8 + t) * 64 + nt * 8 + g]);
        v.y = cvt_tf32(Ww[(ks * 8 + t + 4) * 64 + nt * 8 + g]);
        g_Wfrag[idx] = v;
    }
}

__global__ __launch_bounds__(256, 4) void gat_kernel(
    const float* __restrict__ nodes,
    const float* __restrict__ edges,
    const float* __restrict__ Wbias,
    const float* __restrict__ attw,
    const float* __restrict__ gamma,
    const float* __restrict__ beta,
    float* __restrict__ out)
{
    __shared__ float  sN[4][33 * RS];        // nodes, pre-rounded to tf32 (35.9 KB)
    __shared__ uint2  sB[8 * 8 * 32];        // weight fragments (16 KB)
    __shared__ float2 sSum[4][2][33];        // (sum, sumsq) per row/half (2.1 KB)
    __shared__ float  sScore[4][2][32];      // attention scores rows 1..32 (1 KB)
    __shared__ float  sAttn[4][32];
    __shared__ float2 sT[4][2];              // target LN partials per half

    const int tid  = threadIdx.x;
    const int lane = tid & 31;
    const int warp = tid >> 5;
    const int bl   = warp >> 1;     // batch within CTA (0..3)
    const int half = warp & 1;      // column half (32 cols)
    const int t    = lane & 3;      // threadID-in-group
    const int g    = lane >> 2;     // groupID
    const long long b = (long long)blockIdx.x * 4 + bl;
    const int barid = bl + 1;

    // ---- stage weights (16 KB, once per CTA / 4 batches) ----
    for (int q = tid; q < 2048; q += 256) sB[q] = g_Wfrag[q];

    // ---- stage nodes, pre-converted to tf32: 4 batches x 528 float4 ----
    const float* gNall = nodes + (long long)blockIdx.x * 4 * 2112;
#pragma unroll
    for (int bb = 0; bb < 4; ++bb) {
        const float4* src = (const float4*)(gNall + bb * 2112);
#pragma unroll
        for (int qq = 0; qq < 3; ++qq) {
            int q = tid + qq * 256;
            if (q < 528) {
                float4 v = src[q];
                float4 w;
                w.x = __uint_as_float(cvt_tf32(v.x));
                w.y = __uint_as_float(cvt_tf32(v.y));
                w.z = __uint_as_float(cvt_tf32(v.z));
                w.w = __uint_as_float(cvt_tf32(v.w));
                int r = q >> 4, i4 = q & 15;
                *(float4*)&sN[bb][r * RS + i4 * 4] = w;
            }
        }
    }

    // ---- edge score term (half==0 warps, lane = neighbor k) ----
    float ek = 0.f;
    if (half == 0) {
        const float4* er = (const float4*)(edges + (b * 32 + lane) * 16);
#pragma unroll
        for (int e4 = 0; e4 < 4; ++e4) {
            float4 a = er[e4];
            float4 w = *(const float4*)&g_ewproj[e4 * 4];
            ek += a.x * w.x + a.y * w.y + a.z * w.z + a.w * w.w;
        }
    }

    __syncthreads();  // staging complete (CTA-wide, once)

    // ---- tensor-core GEMM: 3 m16 tiles x 4 n8 tiles (this warp's half) ----
    const unsigned* sNb = (const unsigned*)sN[bl];
    float d[3][4][4];
#pragma unroll
    for (int m = 0; m < 3; ++m)
#pragma unroll
        for (int j = 0; j < 4; ++j)
#pragma unroll
            for (int c = 0; c < 4; ++c) d[m][j][c] = 0.f;

#pragma unroll
    for (int ks = 0; ks < 8; ++ks) {
        unsigned bb[4][2];
#pragma unroll
        for (int j = 0; j < 4; ++j) {
            uint2 v = sB[(ks * 8 + half * 4 + j) * 32 + lane];
            bb[j][0] = v.x; bb[j][1] = v.y;
        }
        unsigned aa[3][4];
#pragma unroll
        for (int m = 0; m < 2; ++m) {
            int base = (m * 16 + g) * RS + ks * 8 + t;
            aa[m][0] = sNb[base];
            aa[m][1] = sNb[base + 8 * RS];
            aa[m][2] = sNb[base + 4];
            aa[m][3] = sNb[base + 8 * RS + 4];
        }
        if (g == 0) {   // m-tile 2: only row 32 real
            int base = 32 * RS + ks * 8 + t;
            aa[2][0] = sNb[base];
            aa[2][2] = sNb[base + 4];
        } else { aa[2][0] = 0u; aa[2][2] = 0u; }
        aa[2][1] = 0u; aa[2][3] = 0u;

#pragma unroll
        for (int m = 0; m < 3; ++m)
#pragma unroll
            for (int j = 0; j < 4; ++j)
                MMA_TF32(d[m][j], aa[m], bb[j]);
    }

    // ---- epilogue params (post-GEMM to keep mainloop registers lean) ----
    const int col0 = half * 32 + 2 * t;
    float2 wb2[4], aw2[4], g2[4], be2[4];
#pragma unroll
    for (int j = 0; j < 4; ++j) {
        wb2[j] = *(const float2*)(Wbias + col0 + j * 8);
        aw2[j] = *(const float2*)(attw + 64 + col0 + j * 8);
        g2[j]  = *(const float2*)(gamma + col0 + j * 8);
        be2[j] = *(const float2*)(beta  + col0 + j * 8);
    }

    // ---- add bias; per-row stats (sum, sumsq, score) ----
#pragma unroll
    for (int m = 0; m < 3; ++m)
#pragma unroll
        for (int j = 0; j < 4; ++j) {
            d[m][j][0] += wb2[j].x; d[m][j][1] += wb2[j].y;
            d[m][j][2] += wb2[j].x; d[m][j][3] += wb2[j].y;
        }

    float sm[3][2], s2[3][2], sc[3][2];
#pragma unroll
    for (int m = 0; m < 3; ++m)
#pragma unroll
        for (int rh = 0; rh < 2; ++rh) {
            float a = 0.f, q = 0.f, s = 0.f;
#pragma unroll
            for (int j = 0; j < 4; ++j) {
                float h0 = d[m][j][rh * 2], h1 = d[m][j][rh * 2 + 1];
                a += h0 + h1;
                q = fmaf(h0, h0, fmaf(h1, h1, q));
                s = fmaf(h0, aw2[j].x, fmaf(h1, aw2[j].y, s));
            }
#pragma unroll
            for (int dl = 1; dl <= 2; dl <<= 1) {
                a += __shfl_xor_sync(0xffffffffu, a, dl);
                q += __shfl_xor_sync(0xffffffffu, q, dl);
                s += __shfl_xor_sync(0xffffffffu, s, dl);
            }
            sm[m][rh] = a; s2[m][rh] = q; sc[m][rh] = s;
        }
    if (t == 0) {
        sSum[bl][half][g]      = make_float2(sm[0][0], s2[0][0]);
        sSum[bl][half][g + 8]  = make_float2(sm[0][1], s2[0][1]);
        sSum[bl][half][g + 16] = make_float2(sm[1][0], s2[1][0]);
        sSum[bl][half][g + 24] = make_float2(sm[1][1], s2[1][1]);
        // scores stored at [row-1] for rows 1..32
        if (g > 0) sScore[bl][half][g - 1] = sc[0][0];
        sScore[bl][half][g + 7]  = sc[0][1];   // row g+8
        sScore[bl][half][g + 15] = sc[1][0];   // row 16+g
        sScore[bl][half][g + 23] = sc[1][1];   // row 24+g
        if (g == 0) {
            sSum[bl][half][32]   = make_float2(sm[2][0], s2[2][0]);
            sScore[bl][half][31] = sc[2][0];   // row 32
        }
    }
    BARX(barid);   // only this batch's 2 warps

    // ---- layernorm + store for neighbor rows (1..32) ----
    float* gO = out + b * 2112;
#pragma unroll
    for (int m = 0; m < 3; ++m)
#pragma unroll
        for (int rh = 0; rh < 2; ++rh) {
            int row = m * 16 + g + rh * 8;
            bool valid = (row >= 1) && (row <= 32) && !(m == 2 && !(g == 0 && rh == 0));
            if (valid) {
                float2 u0 = sSum[bl][0][row];
                float2 u1 = sSum[bl][1][row];
                float mu  = (u0.x + u1.x) * (1.f / 64.f);
                float var = fmaf(u0.y + u1.y, 1.f / 64.f, -mu * mu);
                float ri  = rsqrtf(var + EPSLN);
#pragma unroll
                for (int j = 0; j < 4; ++j) {
                    float2 o;
                    o.x = fmaf((d[m][j][rh * 2]     - mu) * ri, g2[j].x, be2[j].x);
                    o.y = fmaf((d[m][j][rh * 2 + 1] - mu) * ri, g2[j].y, be2[j].y);
                    *(float2*)(gO + row * 64 + col0 + j * 8) = o;
                }
            }
        }

    // ---- softmax over 32 neighbor scores (half==0 warp of each batch) ----
    if (half == 0) {
        float s = sScore[bl][0][lane] + sScore[bl][1][lane] + ek;
        float mx = s;
#pragma unroll
        for (int dl = 16; dl > 0; dl >>= 1) mx = fmaxf(mx, __shfl_xor_sync(0xffffffffu, mx, dl));
        float p = __expf(s - mx);
        float tot = p;
#pragma unroll
        for (int dl = 16; dl > 0; dl >>= 1) tot += __shfl_xor_sync(0xffffffffu, tot, dl);
        sAttn[bl][lane] = p / tot;
    }
    BARX(barid);

    // ---- messages: msg[col] = sum_k attn_k * h_k[col] ----
    float aA = (g > 0) ? sAttn[bl][g - 1] : 0.f;   // row g
    float aB = sAttn[bl][g + 7];                    // row g+8
    float aC = sAttn[bl][g + 15];                   // row 16+g
    float aD = sAttn[bl][g + 23];                   // row 24+g
    float aE = (g == 0) ? sAttn[bl][31] : 0.f;      // row 32

    float pm[4][2];
#pragma unroll
    for (int j = 0; j < 4; ++j)
#pragma unroll
        for (int c = 0; c < 2; ++c) {
            float v = aA * d[0][j][c] + aB * d[0][j][2 + c]
                    + aC * d[1][j][c] + aD * d[1][j][2 + c]
                    + aE * d[2][j][c];
#pragma unroll
            for (int dl = 4; dl <= 16; dl <<= 1)
                v += __shfl_xor_sync(0xffffffffu, v, dl);
            pm[j][c] = v;
        }

    // ---- target row 0 (held by g==0 lanes) ----
    float tv[4][2];
    float tsm = 0.f, ts2 = 0.f;
#pragma unroll
    for (int j = 0; j < 4; ++j)
#pragma unroll
        for (int c = 0; c < 2; ++c) {
            float v = d[0][j][c] + pm[j][c];
            tv[j][c] = v;
            tsm += v;
            ts2 = fmaf(v, v, ts2);
        }
#pragma unroll
    for (int dl = 1; dl <= 2; dl <<= 1) {
        tsm += __shfl_xor_sync(0xffffffffu, tsm, dl);
        ts2 += __shfl_xor_sync(0xffffffffu, ts2, dl);
    }
    if (lane == 0) sT[bl][half] = make_float2(tsm, ts2);
    BARX(barid);

    if (lane < 4) {  // g==0, t=0..3 lanes write target row
        float2 v0 = sT[bl][0], v1 = sT[bl][1];
        float mu  = (v0.x + v1.x) * (1.f / 64.f);
        float var = fmaf(v0.y + v1.y, 1.f / 64.f, -mu * mu);
        float ri  = rsqrtf(var + EPSLN);
#pragma unroll
        for (int j = 0; j < 4; ++j) {
            float2 o;
            o.x = fmaf((tv[j][0] - mu) * ri, g2[j].x, be2[j].x);
            o.y = fmaf((tv[j][1] - mu) * ri, g2[j].y, be2[j].y);
            *(float2*)(gO + col0 + j * 8) = o;
        }
    }
}

extern "C" void kernel_launch(void* const* d_in, const int* in_sizes, int n_in,
                              void* d_out, int out_size) {
    const float* nodes = (const float*)d_in[0];
    const float* edges = (const float*)d_in[1];
    const float* Ww    = (const float*)d_in[2];
    const float* Wb    = (const float*)d_in[3];
    const float* Wew   = (const float*)d_in[4];
    // d_in[5] = We_b   (cancels under softmax shift-invariance)
    const float* attw  = (const float*)d_in[6];
    // d_in[7] = attn_b (cancels under softmax shift-invariance)
    const float* gamma = (const float*)d_in[8];
    const float* beta  = (const float*)d_in[9];

    prep_kernel<<<1, 256>>>(Ww, Wew, attw);
    gat_kernel<<<16384 / 4, 256>>>(nodes, edges, Wb, attw, gamma, beta, (float*)d_out);
}

// round 9
// speedup vs baseline: 1.4975x; 1.4975x over previous
#include <cuda_runtime.h>

#define EPSLN 1e-5f
#define RS 68   // smem row stride in floats (4g+t bank pattern -> conflict-free)

// Precomputed per launch (deterministic, graph-capturable)
// B fragment for m16n8k8.row.col: b0 = W[ks*8+t][nt*8+g], b1 = W[ks*8+t+4][nt*8+g]
__device__ __align__(16) uint2 g_Wfrag[8 * 8 * 32];
__device__ __align__(16) float g_ewproj[16];         // We_w @ attn_w[128:192]

__device__ __forceinline__ unsigned cvt_tf32(float x) {
    unsigned r; asm("cvt.rna.tf32.f32 %0, %1;" : "=r"(r) : "f"(x)); return r;
}

#define MMA_TF32(d, a, b)                                                          \
    asm volatile(                                                                  \
        "mma.sync.aligned.m16n8k8.row.col.f32.tf32.tf32.f32 "                      \
        "{%0,%1,%2,%3},{%4,%5,%6,%7},{%8,%9},{%0,%1,%2,%3};"                       \
        : "+f"(d[0]), "+f"(d[1]), "+f"(d[2]), "+f"(d[3])                           \
        : "r"(a[0]), "r"(a[1]), "r"(a[2]), "r"(a[3]), "r"(b[0]), "r"(b[1]))

// Named barrier over the 64 threads (2 warps) serving one batch
#define BARX(id) asm volatile("bar.sync %0, 64;" :: "r"(id) : "memory")

#define CP_ASYNC16(dst_u32, src_ptr)                                               \
    asm volatile("cp.async.cg.shared.global [%0], [%1], 16;"                       \
                 :: "r"(dst_u32), "l"(src_ptr))

__global__ void prep_kernel(const float* __restrict__ Ww,
                            const float* __restrict__ Wew,
                            const float* __restrict__ attw) {
    int tid = threadIdx.x;  // 256
    if (tid < 16) {
        float se = 0.f;
#pragma unroll 8
        for (int o = 0; o < 64; ++o) se += Wew[tid * 64 + o] * attw[128 + o];
        g_ewproj[tid] = se;
    }
    for (int idx = tid; idx < 2048; idx += 256) {
        int lane = idx & 31;
        int nt   = (idx >> 5) & 7;
        int ks   = idx >> 8;
        int t = lane & 3, g = lane >> 2;
        uint2 v;
        v.x = cvt_tf32(Ww[(ks * 8 + t) * 64 + nt * 8 + g]);
        v.y = cvt_tf32(Ww[(ks * 8 + t + 4) * 64 + nt * 8 + g]);
        g_Wfrag[idx] = v;
    }
}

__global__ __launch_bounds__(256, 3) void gat_kernel(
    const float* __restrict__ nodes,
    const float* __restrict__ edges,
    const float* __restrict__ Wbias,
    const float* __restrict__ attw,
    const float* __restrict__ gamma,
    const float* __restrict__ beta,
    float* __restrict__ out)
{
    __shared__ float  sN[4][33 * RS];        // nodes, raw fp32 (cvt in mainloop)
    __shared__ uint2  sB[8 * 8 * 32];        // weight fragments (16 KB)
    __shared__ float2 sSum[4][2][33];        // (sum, sumsq) per row/half
    __shared__ float  sScore[4][2][32];      // attention scores rows 1..32
    __shared__ float  sAttn[4][32];
    __shared__ float2 sT[4][2];              // target LN partials per half

    const int tid  = threadIdx.x;
    const int lane = tid & 31;
    const int warp = tid >> 5;
    const int bl   = warp >> 1;     // batch within CTA (0..3)
    const int half = warp & 1;      // column half (32 cols)
    const int t    = lane & 3;      // threadID-in-group
    const int g    = lane >> 2;     // groupID
    const long long b = (long long)blockIdx.x * 4 + bl;
    const int barid = bl + 1;

    // ---- stage nodes via cp.async (no RF round-trip, no STS wavefronts) ----
    // 4 contiguous batches = 2112 float4 total
    const float4* srcAll = (const float4*)(nodes + (long long)blockIdx.x * 4 * 2112);
#pragma unroll
    for (int qq = 0; qq < 9; ++qq) {
        int q = tid + qq * 256;
        if (q < 2112) {
            int bb = q / 528;
            int ql = q - bb * 528;
            int r  = ql >> 4, i4 = ql & 15;
            unsigned dst = (unsigned)__cvta_generic_to_shared(&sN[bb][r * RS + i4 * 4]);
            CP_ASYNC16(dst, srcAll + q);
        }
    }
    asm volatile("cp.async.commit_group;" ::: "memory");

    // ---- stage weights (16 KB, once per CTA / 4 batches) ----
    for (int q = tid; q < 2048; q += 256) sB[q] = g_Wfrag[q];

    // ---- edge score term (half==0 warps, lane = neighbor k) ----
    float ek = 0.f;
    if (half == 0) {
        const float4* er = (const float4*)(edges + (b * 32 + lane) * 16);
#pragma unroll
        for (int e4 = 0; e4 < 4; ++e4) {
            float4 a = er[e4];
            float4 w = *(const float4*)&g_ewproj[e4 * 4];
            ek += a.x * w.x + a.y * w.y + a.z * w.z + a.w * w.w;
        }
    }

    asm volatile("cp.async.wait_group 0;" ::: "memory");
    __syncthreads();  // staging complete (CTA-wide, once)

    // ---- tensor-core GEMM: 3 m16 tiles x 4 n8 tiles (this warp's half) ----
    const float* sNb = sN[bl];
    float d[3][4][4];
#pragma unroll
    for (int m = 0; m < 3; ++m)
#pragma unroll
        for (int j = 0; j < 4; ++j)
#pragma unroll
            for (int c = 0; c < 4; ++c) d[m][j][c] = 0.f;

#pragma unroll
    for (int ks = 0; ks < 8; ++ks) {
        unsigned bb[4][2];
#pragma unroll
        for (int j = 0; j < 4; ++j) {
            uint2 v = sB[(ks * 8 + half * 4 + j) * 32 + lane];
            bb[j][0] = v.x; bb[j][1] = v.y;
        }
        unsigned aa[3][4];
#pragma unroll
        for (int m = 0; m < 2; ++m) {
            int base = (m * 16 + g) * RS + ks * 8 + t;
            aa[m][0] = cvt_tf32(sNb[base]);
            aa[m][1] = cvt_tf32(sNb[base + 8 * RS]);
            aa[m][2] = cvt_tf32(sNb[base + 4]);
            aa[m][3] = cvt_tf32(sNb[base + 8 * RS + 4]);
        }
        if (g == 0) {   // m-tile 2: only row 32 real
            int base = 32 * RS + ks * 8 + t;
            aa[2][0] = cvt_tf32(sNb[base]);
            aa[2][2] = cvt_tf32(sNb[base + 4]);
        } else { aa[2][0] = 0u; aa[2][2] = 0u; }
        aa[2][1] = 0u; aa[2][3] = 0u;

#pragma unroll
        for (int m = 0; m < 3; ++m)
#pragma unroll
            for (int j = 0; j < 4; ++j)
                MMA_TF32(d[m][j], aa[m], bb[j]);
    }

    // ---- epilogue params (post-GEMM to keep mainloop registers lean) ----
    const int col0 = half * 32 + 2 * t;
    float2 wb2[4], aw2[4], g2[4], be2[4];
#pragma unroll
    for (int j = 0; j < 4; ++j) {
        wb2[j] = *(const float2*)(Wbias + col0 + j * 8);
        aw2[j] = *(const float2*)(attw + 64 + col0 + j * 8);
        g2[j]  = *(const float2*)(gamma + col0 + j * 8);
        be2[j] = *(const float2*)(beta  + col0 + j * 8);
    }

    // ---- add bias; per-row stats (sum, sumsq, score) ----
#pragma unroll
    for (int m = 0; m < 3; ++m)
#pragma unroll
        for (int j = 0; j < 4; ++j) {
            d[m][j][0] += wb2[j].x; d[m][j][1] += wb2[j].y;
            d[m][j][2] += wb2[j].x; d[m][j][3] += wb2[j].y;
        }

    float sm[3][2], s2[3][2], sc[3][2];
#pragma unroll
    for (int m = 0; m < 3; ++m)
#pragma unroll
        for (int rh = 0; rh < 2; ++rh) {
            float a = 0.f, q = 0.f, s = 0.f;
#pragma unroll
            for (int j = 0; j < 4; ++j) {
                float h0 = d[m][j][rh * 2], h1 = d[m][j][rh * 2 + 1];
                a += h0 + h1;
                q = fmaf(h0, h0, fmaf(h1, h1, q));
                s = fmaf(h0, aw2[j].x, fmaf(h1, aw2[j].y, s));
            }
#pragma unroll
            for (int dl = 1; dl <= 2; dl <<= 1) {
                a += __shfl_xor_sync(0xffffffffu, a, dl);
                q += __shfl_xor_sync(0xffffffffu, q, dl);
                s += __shfl_xor_sync(0xffffffffu, s, dl);
            }
            sm[m][rh] = a; s2[m][rh] = q; sc[m][rh] = s;
        }
    if (t == 0) {
        sSum[bl][half][g]      = make_float2(sm[0][0], s2[0][0]);
        sSum[bl][half][g + 8]  = make_float2(sm[0][1], s2[0][1]);
        sSum[bl][half][g + 16] = make_float2(sm[1][0], s2[1][0]);
        sSum[bl][half][g + 24] = make_float2(sm[1][1], s2[1][1]);
        if (g > 0) sScore[bl][half][g - 1] = sc[0][0];
        sScore[bl][half][g + 7]  = sc[0][1];   // row g+8
        sScore[bl][half][g + 15] = sc[1][0];   // row 16+g
        sScore[bl][half][g + 23] = sc[1][1];   // row 24+g
        if (g == 0) {
            sSum[bl][half][32]   = make_float2(sm[2][0], s2[2][0]);
            sScore[bl][half][31] = sc[2][0];   // row 32
        }
    }
    BARX(barid);   // only this batch's 2 warps

    // ---- layernorm + store for neighbor rows (1..32) ----
    float* gO = out + b * 2112;
#pragma unroll
    for (int m = 0; m < 3; ++m)
#pragma unroll
        for (int rh = 0; rh < 2; ++rh) {
            int row = m * 16 + g + rh * 8;
            bool valid = (row >= 1) && (row <= 32) && !(m == 2 && !(g == 0 && rh == 0));
            if (valid) {
                float2 u0 = sSum[bl][0][row];
                float2 u1 = sSum[bl][1][row];
                float mu  = (u0.x + u1.x) * (1.f / 64.f);
                float var = fmaf(u0.y + u1.y, 1.f / 64.f, -mu * mu);
                float ri  = rsqrtf(var + EPSLN);
#pragma unroll
                for (int j = 0; j < 4; ++j) {
                    float2 o;
                    o.x = fmaf((d[m][j][rh * 2]     - mu) * ri, g2[j].x, be2[j].x);
                    o.y = fmaf((d[m][j][rh * 2 + 1] - mu) * ri, g2[j].y, be2[j].y);
                    *(float2*)(gO + row * 64 + col0 + j * 8) = o;
                }
            }
        }

    // ---- softmax over 32 neighbor scores (half==0 warp of each batch) ----
    if (half == 0) {
        float s = sScore[bl][0][lane] + sScore[bl][1][lane] + ek;
        float mx = s;
#pragma unroll
        for (int dl = 16; dl > 0; dl >>= 1) mx = fmaxf(mx, __shfl_xor_sync(0xffffffffu, mx, dl));
        float p = __expf(s - mx);
        float tot = p;
#pragma unroll
        for (int dl = 16; dl > 0; dl >>= 1) tot += __shfl_xor_sync(0xffffffffu, tot, dl);
        sAttn[bl][lane] = p / tot;
    }
    BARX(barid);

    // ---- messages: msg[col] = sum_k attn_k * h_k[col] ----
    float aA = (g > 0) ? sAttn[bl][g - 1] : 0.f;   // row g
    float aB = sAttn[bl][g + 7];                    // row g+8
    float aC = sAttn[bl][g + 15];                   // row 16+g
    float aD = sAttn[bl][g + 23];                   // row 24+g
    float aE = (g == 0) ? sAttn[bl][31] : 0.f;      // row 32

    float pm[4][2];
#pragma unroll
    for (int j = 0; j < 4; ++j)
#pragma unroll
        for (int c = 0; c < 2; ++c) {
            float v = aA * d[0][j][c] + aB * d[0][j][2 + c]
                    + aC * d[1][j][c] + aD * d[1][j][2 + c]
                    + aE * d[2][j][c];
#pragma unroll
            for (int dl = 4; dl <= 16; dl <<= 1)
                v += __shfl_xor_sync(0xffffffffu, v, dl);
            pm[j][c] = v;
        }

    // ---- target row 0 (held by g==0 lanes) ----
    float tv[4][2];
    float tsm = 0.f, ts2 = 0.f;
#pragma unroll
    for (int j = 0; j < 4; ++j)
#pragma unroll
        for (int c = 0; c < 2; ++c) {
            float v = d[0][j][c] + pm[j][c];
            tv[j][c] = v;
            tsm += v;
            ts2 = fmaf(v, v, ts2);
        }
#pragma unroll
    for (int dl = 1; dl <= 2; dl <<= 1) {
        tsm += __shfl_xor_sync(0xffffffffu, tsm, dl);
        ts2 += __shfl_xor_sync(0xffffffffu, ts2, dl);
    }
    if (lane == 0) sT[bl][half] = make_float2(tsm, ts2);
    BARX(barid);

    if (lane < 4) {  // g==0, t=0..3 lanes write target row
        float2 v0 = sT[bl][0], v1 = sT[bl][1];
        float mu  = (v0.x + v1.x) * (1.f / 64.f);
        float var = fmaf(v0.y + v1.y, 1.f / 64.f, -mu * mu);
        float ri  = rsqrtf(var + EPSLN);
#pragma unroll
        for (int j = 0; j < 4; ++j) {
            float2 o;
            o.x = fmaf((tv[j][0] - mu) * ri, g2[j].x, be2[j].x);
            o.y = fmaf((tv[j][1] - mu) * ri, g2[j].y, be2[j].y);
            *(float2*)(gO + col0 + j * 8) = o;
        }
    }
}

extern "C" void kernel_launch(void* const* d_in, const int* in_sizes, int n_in,
                              void* d_out, int out_size) {
    const float* nodes = (const float*)d_in[0];
    const float* edges = (const float*)d_in[1];
    const float* Ww    = (const float*)d_in[2];
    const float* Wb    = (const float*)d_in[3];
    const float* Wew   = (const float*)d_in[4];
    // d_in[5] = We_b   (cancels under softmax shift-invariance)
    const float* attw  = (const float*)d_in[6];
    // d_in[7] = attn_b (cancels under softmax shift-invariance)
    const float* gamma = (const float*)d_in[8];
    const float* beta  = (const float*)d_in[9];

    prep_kernel<<<1, 256>>>(Ww, Wew, attw);
    gat_kernel<<<16384 / 4, 256>>>(nodes, edges, Wb, attw, gamma, beta, (float*)d_out);
}

// round 10
// speedup vs baseline: 1.5672x; 1.0465x over previous
#include <cuda_runtime.h>

#define EPSLN 1e-5f
#define RS 68   // smem row stride in floats (4g+t bank pattern -> conflict-free)

// Precomputed per launch (deterministic, graph-capturable)
// B fragment for m16n8k8.row.col: b0 = W[ks*8+t][nt*8+g], b1 = W[ks*8+t+4][nt*8+g]
__device__ __align__(16) uint2 g_Wfrag[8 * 8 * 32];
__device__ __align__(16) float g_ewproj[16];         // We_w @ attn_w[128:192]

__device__ __forceinline__ unsigned cvt_tf32(float x) {
    unsigned r; asm("cvt.rna.tf32.f32 %0, %1;" : "=r"(r) : "f"(x)); return r;
}

#define MMA_TF32(d, a, b)                                                          \
    asm volatile(                                                                  \
        "mma.sync.aligned.m16n8k8.row.col.f32.tf32.tf32.f32 "                      \
        "{%0,%1,%2,%3},{%4,%5,%6,%7},{%8,%9},{%0,%1,%2,%3};"                       \
        : "+f"(d[0]), "+f"(d[1]), "+f"(d[2]), "+f"(d[3])                           \
        : "r"(a[0]), "r"(a[1]), "r"(a[2]), "r"(a[3]), "r"(b[0]), "r"(b[1]))

// Named barrier over the 64 threads (2 warps) serving one batch
#define BARX(id) asm volatile("bar.sync %0, 64;" :: "r"(id) : "memory")

#define CP_ASYNC16(dst_u32, src_ptr)                                               \
    asm volatile("cp.async.cg.shared.global [%0], [%1], 16;"                       \
                 :: "r"(dst_u32), "l"(src_ptr))

__global__ void prep_kernel(const float* __restrict__ Ww,
                            const float* __restrict__ Wew,
                            const float* __restrict__ attw) {
    int tid = threadIdx.x;  // 256
    if (tid < 16) {
        float se = 0.f;
#pragma unroll 8
        for (int o = 0; o < 64; ++o) se += Wew[tid * 64 + o] * attw[128 + o];
        g_ewproj[tid] = se;
    }
    for (int idx = tid; idx < 2048; idx += 256) {
        int lane = idx & 31;
        int nt   = (idx >> 5) & 7;
        int ks   = idx >> 8;
        int t = lane & 3, g = lane >> 2;
        uint2 v;
        v.x = cvt_tf32(Ww[(ks * 8 + t) * 64 + nt * 8 + g]);
        v.y = cvt_tf32(Ww[(ks * 8 + t + 4) * 64 + nt * 8 + g]);
        g_Wfrag[idx] = v;
    }
}

__global__ __launch_bounds__(256, 3) void gat_kernel(
    const float* __restrict__ nodes,
    const float* __restrict__ edges,
    const float* __restrict__ Wbias,
    const float* __restrict__ attw,
    const float* __restrict__ gamma,
    const float* __restrict__ beta,
    float* __restrict__ out)
{
    __shared__ float  sN[4][33 * RS];        // nodes, raw fp32 (MMA truncates to tf32)
    __shared__ uint2  sB[8 * 8 * 32];        // weight fragments (16 KB)
    __shared__ float2 sSum[4][2][33];        // (sum, sumsq) per row/half
    __shared__ float  sScore[4][2][32];      // attention scores rows 1..32
    __shared__ float  sAttn[4][32];
    __shared__ float2 sT[4][2];              // target LN partials per half

    const int tid  = threadIdx.x;
    const int lane = tid & 31;
    const int warp = tid >> 5;
    const int bl   = warp >> 1;     // batch within CTA (0..3)
    const int half = warp & 1;      // column half (32 cols)
    const int t    = lane & 3;      // threadID-in-group
    const int g    = lane >> 2;     // groupID
    const long long b = (long long)blockIdx.x * 4 + bl;
    const int barid = bl + 1;

    // ---- stage nodes via cp.async (no RF round-trip, no STS wavefronts) ----
    const float4* srcAll = (const float4*)(nodes + (long long)blockIdx.x * 4 * 2112);
#pragma unroll
    for (int qq = 0; qq < 9; ++qq) {
        int q = tid + qq * 256;
        if (q < 2112) {
            int bb = q / 528;
            int ql = q - bb * 528;
            int r  = ql >> 4, i4 = ql & 15;
            unsigned dst = (unsigned)__cvta_generic_to_shared(&sN[bb][r * RS + i4 * 4]);
            CP_ASYNC16(dst, srcAll + q);
        }
    }
    asm volatile("cp.async.commit_group;" ::: "memory");

    // ---- stage weights (16 KB, once per CTA / 4 batches) ----
    for (int q = tid; q < 2048; q += 256) sB[q] = g_Wfrag[q];

    // ---- edge score term (half==0 warps, lane = neighbor k) ----
    float ek = 0.f;
    if (half == 0) {
        const float4* er = (const float4*)(edges + (b * 32 + lane) * 16);
#pragma unroll
        for (int e4 = 0; e4 < 4; ++e4) {
            float4 a = er[e4];
            float4 w = *(const float4*)&g_ewproj[e4 * 4];
            ek += a.x * w.x + a.y * w.y + a.z * w.z + a.w * w.w;
        }
    }

    asm volatile("cp.async.wait_group 0;" ::: "memory");
    __syncthreads();  // staging complete (CTA-wide, once)

    // ---- tensor-core GEMM: 3 m16 tiles x 4 n8 tiles (this warp's half) ----
    // A operands fed as raw fp32 bits (HW reads top 19 bits = tf32 truncation).
    const unsigned* sNb = (const unsigned*)sN[bl];
    float d[3][4][4];
#pragma unroll
    for (int m = 0; m < 3; ++m)
#pragma unroll
        for (int j = 0; j < 4; ++j)
#pragma unroll
            for (int c = 0; c < 4; ++c) d[m][j][c] = 0.f;

#pragma unroll
    for (int ks = 0; ks < 8; ++ks) {
        unsigned bb[4][2];
#pragma unroll
        for (int j = 0; j < 4; ++j) {
            uint2 v = sB[(ks * 8 + half * 4 + j) * 32 + lane];
            bb[j][0] = v.x; bb[j][1] = v.y;
        }
        unsigned aa[3][4];
#pragma unroll
        for (int m = 0; m < 2; ++m) {
            int base = (m * 16 + g) * RS + ks * 8 + t;
            aa[m][0] = sNb[base];
            aa[m][1] = sNb[base + 8 * RS];
            aa[m][2] = sNb[base + 4];
            aa[m][3] = sNb[base + 8 * RS + 4];
        }
        if (g == 0) {   // m-tile 2: only row 32 real
            int base = 32 * RS + ks * 8 + t;
            aa[2][0] = sNb[base];
            aa[2][2] = sNb[base + 4];
        } else { aa[2][0] = 0u; aa[2][2] = 0u; }
        aa[2][1] = 0u; aa[2][3] = 0u;

#pragma unroll
        for (int m = 0; m < 3; ++m)
#pragma unroll
            for (int j = 0; j < 4; ++j)
                MMA_TF32(d[m][j], aa[m], bb[j]);
    }

    // ---- epilogue params (post-GEMM to keep mainloop registers lean) ----
    const int col0 = half * 32 + 2 * t;
    float2 wb2[4], aw2[4], g2[4], be2[4];
#pragma unroll
    for (int j = 0; j < 4; ++j) {
        wb2[j] = *(const float2*)(Wbias + col0 + j * 8);
        aw2[j] = *(const float2*)(attw + 64 + col0 + j * 8);
        g2[j]  = *(const float2*)(gamma + col0 + j * 8);
        be2[j] = *(const float2*)(beta  + col0 + j * 8);
    }

    // ---- add bias; per-row stats (sum, sumsq, score) ----
#pragma unroll
    for (int m = 0; m < 3; ++m)
#pragma unroll
        for (int j = 0; j < 4; ++j) {
            d[m][j][0] += wb2[j].x; d[m][j][1] += wb2[j].y;
            d[m][j][2] += wb2[j].x; d[m][j][3] += wb2[j].y;
        }

    float sm[3][2], s2[3][2], sc[3][2];
#pragma unroll
    for (int m = 0; m < 3; ++m)
#pragma unroll
        for (int rh = 0; rh < 2; ++rh) {
            float a = 0.f, q = 0.f, s = 0.f;
#pragma unroll
            for (int j = 0; j < 4; ++j) {
                float h0 = d[m][j][rh * 2], h1 = d[m][j][rh * 2 + 1];
                a += h0 + h1;
                q = fmaf(h0, h0, fmaf(h1, h1, q));
                s = fmaf(h0, aw2[j].x, fmaf(h1, aw2[j].y, s));
            }
#pragma unroll
            for (int dl = 1; dl <= 2; dl <<= 1) {
                a += __shfl_xor_sync(0xffffffffu, a, dl);
                q += __shfl_xor_sync(0xffffffffu, q, dl);
                s += __shfl_xor_sync(0xffffffffu, s, dl);
            }
            sm[m][rh] = a; s2[m][rh] = q; sc[m][rh] = s;
        }
    if (t == 0) {
        sSum[bl][half][g]      = make_float2(sm[0][0], s2[0][0]);
        sSum[bl][half][g + 8]  = make_float2(sm[0][1], s2[0][1]);
        sSum[bl][half][g + 16] = make_float2(sm[1][0], s2[1][0]);
        sSum[bl][half][g + 24] = make_float2(sm[1][1], s2[1][1]);
        if (g > 0) sScore[bl][half][g - 1] = sc[0][0];
        sScore[bl][half][g + 7]  = sc[0][1];   // row g+8
        sScore[bl][half][g + 15] = sc[1][0];   // row 16+g
        sScore[bl][half][g + 23] = sc[1][1];   // row 24+g
        if (g == 0) {
            sSum[bl][half][32]   = make_float2(sm[2][0], s2[2][0]);
            sScore[bl][half][31] = sc[2][0];   // row 32
        }
    }
    BARX(barid);   // only this batch's 2 warps

    // ---- layernorm + store for neighbor rows (1..32) ----
    float* gO = out + b * 2112;
#pragma unroll
    for (int m = 0; m < 3; ++m)
#pragma unroll
        for (int rh = 0; rh < 2; ++rh) {
            int row = m * 16 + g + rh * 8;
            bool valid = (row >= 1) && (row <= 32) && !(m == 2 && !(g == 0 && rh == 0));
            if (valid) {
                float2 u0 = sSum[bl][0][row];
                float2 u1 = sSum[bl][1][row];
                float mu  = (u0.x + u1.x) * (1.f / 64.f);
                float var = fmaf(u0.y + u1.y, 1.f / 64.f, -mu * mu);
                float ri  = rsqrtf(var + EPSLN);
#pragma unroll
                for (int j = 0; j < 4; ++j) {
                    float2 o;
                    o.x = fmaf((d[m][j][rh * 2]     - mu) * ri, g2[j].x, be2[j].x);
                    o.y = fmaf((d[m][j][rh * 2 + 1] - mu) * ri, g2[j].y, be2[j].y);
                    *(float2*)(gO + row * 64 + col0 + j * 8) = o;
                }
            }
        }

    // ---- softmax over 32 neighbor scores (half==0 warp of each batch) ----
    if (half == 0) {
        float s = sScore[bl][0][lane] + sScore[bl][1][lane] + ek;
        float mx = s;
#pragma unroll
        for (int dl = 16; dl > 0; dl >>= 1) mx = fmaxf(mx, __shfl_xor_sync(0xffffffffu, mx, dl));
        float p = __expf(s - mx);
        float tot = p;
#pragma unroll
        for (int dl = 16; dl > 0; dl >>= 1) tot += __shfl_xor_sync(0xffffffffu, tot, dl);
        sAttn[bl][lane] = p / tot;
    }
    BARX(barid);

    // ---- messages: msg[col] = sum_k attn_k * h_k[col] ----
    float aA = (g > 0) ? sAttn[bl][g - 1] : 0.f;   // row g
    float aB = sAttn[bl][g + 7];                    // row g+8
    float aC = sAttn[bl][g + 15];                   // row 16+g
    float aD = sAttn[bl][g + 23];                   // row 24+g
    float aE = (g == 0) ? sAttn[bl][31] : 0.f;      // row 32

    float pm[4][2];
#pragma unroll
    for (int j = 0; j < 4; ++j)
#pragma unroll
        for (int c = 0; c < 2; ++c) {
            float v = aA * d[0][j][c] + aB * d[0][j][2 + c]
                    + aC * d[1][j][c] + aD * d[1][j][2 + c]
                    + aE * d[2][j][c];
#pragma unroll
            for (int dl = 4; dl <= 16; dl <<= 1)
                v += __shfl_xor_sync(0xffffffffu, v, dl);
            pm[j][c] = v;
        }

    // ---- target row 0 (held by g==0 lanes) ----
    float tv[4][2];
    float tsm = 0.f, ts2 = 0.f;
#pragma unroll
    for (int j = 0; j < 4; ++j)
#pragma unroll
        for (int c = 0; c < 2; ++c) {
            float v = d[0][j][c] + pm[j][c];
            tv[j][c] = v;
            tsm += v;
            ts2 = fmaf(v, v, ts2);
        }
#pragma unroll
    for (int dl = 1; dl <= 2; dl <<= 1) {
        tsm += __shfl_xor_sync(0xffffffffu, tsm, dl);
        ts2 += __shfl_xor_sync(0xffffffffu, ts2, dl);
    }
    if (lane == 0) sT[bl][half] = make_float2(tsm, ts2);
    BARX(barid);

    if (lane < 4) {  // g==0, t=0..3 lanes write target row
        float2 v0 = sT[bl][0], v1 = sT[bl][1];
        float mu  = (v0.x + v1.x) * (1.f / 64.f);
        float var = fmaf(v0.y + v1.y, 1.f / 64.f, -mu * mu);
        float ri  = rsqrtf(var + EPSLN);
#pragma unroll
        for (int j = 0; j < 4; ++j) {
            float2 o;
            o.x = fmaf((tv[j][0] - mu) * ri, g2[j].x, be2[j].x);
            o.y = fmaf((tv[j][1] - mu) * ri, g2[j].y, be2[j].y);
            *(float2*)(gO + col0 + j * 8) = o;
        }
    }
}

extern "C" void kernel_launch(void* const* d_in, const int* in_sizes, int n_in,
                              void* d_out, int out_size) {
    const float* nodes = (const float*)d_in[0];
    const float* edges = (const float*)d_in[1];
    const float* Ww    = (const float*)d_in[2];
    const float* Wb    = (const float*)d_in[3];
    const float* Wew   = (const float*)d_in[4];
    // d_in[5] = We_b   (cancels under softmax shift-invariance)
    const float* attw  = (const float*)d_in[6];
    // d_in[7] = attn_b (cancels under softmax shift-invariance)
    const float* gamma = (const float*)d_in[8];
    const float* beta  = (const float*)d_in[9];

    prep_kernel<<<1, 256>>>(Ww, Wew, attw);
    gat_kernel<<<16384 / 4, 256>>>(nodes, edges, Wb, attw, gamma, beta, (float*)d_out);
}

// round 11
// speedup vs baseline: 1.5816x; 1.0091x over previous
#include <cuda_runtime.h>

#define EPSLN 1e-5f
#define RS 68   // smem row stride in floats (4g+t bank pattern -> conflict-free)
#define NGRP 4096
#define GRID 444   // 148 SMs x 3 CTAs, all resident (persistent)

// Precomputed per launch (deterministic, graph-capturable)
// B fragment for m16n8k8.row.col: b0 = W[ks*8+t][nt*8+g], b1 = W[ks*8+t+4][nt*8+g]
__device__ __align__(16) uint2 g_Wfrag[8 * 8 * 32];
__device__ __align__(16) float g_ewproj[16];         // We_w @ attn_w[128:192]

__device__ __forceinline__ unsigned cvt_tf32(float x) {
    unsigned r; asm("cvt.rna.tf32.f32 %0, %1;" : "=r"(r) : "f"(x)); return r;
}

#define MMA_TF32(d, a, b)                                                          \
    asm volatile(                                                                  \
        "mma.sync.aligned.m16n8k8.row.col.f32.tf32.tf32.f32 "                      \
        "{%0,%1,%2,%3},{%4,%5,%6,%7},{%8,%9},{%0,%1,%2,%3};"                       \
        : "+f"(d[0]), "+f"(d[1]), "+f"(d[2]), "+f"(d[3])                           \
        : "r"(a[0]), "r"(a[1]), "r"(a[2]), "r"(a[3]), "r"(b[0]), "r"(b[1]))

// Named barrier over the 64 threads (2 warps) serving one batch
#define BARX(id) asm volatile("bar.sync %0, 64;" :: "r"(id) : "memory")

#define CP_ASYNC16(dst_u32, src_ptr)                                               \
    asm volatile("cp.async.cg.shared.global [%0], [%1], 16;"                       \
                 :: "r"(dst_u32), "l"(src_ptr))

__global__ void prep_kernel(const float* __restrict__ Ww,
                            const float* __restrict__ Wew,
                            const float* __restrict__ attw) {
    int tid = threadIdx.x;  // 128 threads, 16 blocks
    if (blockIdx.x == 0 && tid < 16) {
        float se = 0.f;
#pragma unroll 8
        for (int o = 0; o < 64; ++o) se += Wew[tid * 64 + o] * attw[128 + o];
        g_ewproj[tid] = se;
    }
    int idx = blockIdx.x * 128 + tid;   // 16*128 = 2048 exactly
    {
        int lane = idx & 31;
        int nt   = (idx >> 5) & 7;
        int ks   = idx >> 8;
        int t = lane & 3, g = lane >> 2;
        uint2 v;
        v.x = cvt_tf32(Ww[(ks * 8 + t) * 64 + nt * 8 + g]);
        v.y = cvt_tf32(Ww[(ks * 8 + t + 4) * 64 + nt * 8 + g]);
        g_Wfrag[idx] = v;
    }
}

__global__ __launch_bounds__(256, 3) void gat_kernel(
    const float* __restrict__ nodes,
    const float* __restrict__ edges,
    const float* __restrict__ Wbias,
    const float* __restrict__ attw,
    const float* __restrict__ gamma,
    const float* __restrict__ beta,
    float* __restrict__ out)
{
    __shared__ float  sN[4][33 * RS];        // nodes, raw fp32 (MMA truncates to tf32)
    __shared__ uint2  sB[8 * 8 * 32];        // weight fragments (16 KB)
    __shared__ float2 sSum[4][2][33];        // (sum, sumsq) per row/half
    __shared__ float  sScore[4][2][32];      // attention scores rows 1..32
    __shared__ float  sAttn[4][32];
    __shared__ float2 sT[4][2];              // target LN partials per half

    const int tid  = threadIdx.x;
    const int lane = tid & 31;
    const int warp = tid >> 5;
    const int bl   = warp >> 1;     // batch within group (0..3)
    const int half = warp & 1;      // column half (32 cols)
    const int t    = lane & 3;      // threadID-in-group
    const int g    = lane >> 2;     // groupID
    const int barid = bl + 1;

    // ---- per-thread staging indices (fixed across iterations) ----
    int sq[9], sb_[9], sr[9], si[9];
#pragma unroll
    for (int qq = 0; qq < 9; ++qq) {
        int q = tid + qq * 256;
        sq[qq] = q;
        int bb = q / 528;
        int ql = q - bb * 528;
        sb_[qq] = bb; sr[qq] = ql >> 4; si[qq] = ql & 15;
    }

    // ---- epilogue params (loop-invariant) ----
    const int col0 = half * 32 + 2 * t;
    float2 wb2[4], aw2[4], g2[4], be2[4];
#pragma unroll
    for (int j = 0; j < 4; ++j) {
        wb2[j] = *(const float2*)(Wbias + col0 + j * 8);
        aw2[j] = *(const float2*)(attw + 64 + col0 + j * 8);
        g2[j]  = *(const float2*)(gamma + col0 + j * 8);
        be2[j] = *(const float2*)(beta  + col0 + j * 8);
    }
    float ewp[16];
#pragma unroll
    for (int e = 0; e < 16; ++e) ewp[e] = g_ewproj[e];

    // ---- stage weights once per CTA lifetime ----
    for (int q = tid; q < 2048; q += 256) sB[q] = g_Wfrag[q];

    // ---- prologue: stage first group's nodes + edge term ----
    long long grp = blockIdx.x;
    {
        const float4* src = (const float4*)(nodes + grp * 4 * 2112);
#pragma unroll
        for (int qq = 0; qq < 9; ++qq)
            if (sq[qq] < 2112) {
                unsigned dst = (unsigned)__cvta_generic_to_shared(
                    &sN[sb_[qq]][sr[qq] * RS + si[qq] * 4]);
                CP_ASYNC16(dst, src + sq[qq]);
            }
        asm volatile("cp.async.commit_group;" ::: "memory");
    }
    float ek_cur = 0.f;
    if (half == 0) {
        const float4* er = (const float4*)(edges + ((grp * 4 + bl) * 32 + lane) * 16);
#pragma unroll
        for (int e4 = 0; e4 < 4; ++e4) {
            float4 a = er[e4];
            ek_cur += a.x * ewp[e4 * 4] + a.y * ewp[e4 * 4 + 1]
                    + a.z * ewp[e4 * 4 + 2] + a.w * ewp[e4 * 4 + 3];
        }
    }
    asm volatile("cp.async.wait_group 0;" ::: "memory");
    __syncthreads();

    // ================= persistent loop over groups =================
    for (; grp < NGRP; grp += GRID) {
        const long long b = grp * 4 + bl;

        // ---- tensor-core GEMM: 3 m16 tiles x 4 n8 tiles ----
        const unsigned* sNb = (const unsigned*)sN[bl];
        float d[3][4][4];
#pragma unroll
        for (int m = 0; m < 3; ++m)
#pragma unroll
            for (int j = 0; j < 4; ++j)
#pragma unroll
                for (int c = 0; c < 4; ++c) d[m][j][c] = 0.f;

#pragma unroll
        for (int ks = 0; ks < 8; ++ks) {
            unsigned bb[4][2];
#pragma unroll
            for (int j = 0; j < 4; ++j) {
                uint2 v = sB[(ks * 8 + half * 4 + j) * 32 + lane];
                bb[j][0] = v.x; bb[j][1] = v.y;
            }
            unsigned aa[3][4];
#pragma unroll
            for (int m = 0; m < 2; ++m) {
                int base = (m * 16 + g) * RS + ks * 8 + t;
                aa[m][0] = sNb[base];
                aa[m][1] = sNb[base + 8 * RS];
                aa[m][2] = sNb[base + 4];
                aa[m][3] = sNb[base + 8 * RS + 4];
            }
            if (g == 0) {   // m-tile 2: only row 32 real
                int base = 32 * RS + ks * 8 + t;
                aa[2][0] = sNb[base];
                aa[2][2] = sNb[base + 4];
            } else { aa[2][0] = 0u; aa[2][2] = 0u; }
            aa[2][1] = 0u; aa[2][3] = 0u;

#pragma unroll
            for (int m = 0; m < 3; ++m)
#pragma unroll
                for (int j = 0; j < 4; ++j)
                    MMA_TF32(d[m][j], aa[m], bb[j]);
        }

        __syncthreads();   // all warps done reading sN -> safe to refill

        // ---- prefetch next group's nodes + edge term (hidden by epilogue) ----
        const long long gnext = grp + GRID;
        if (gnext < NGRP) {
            const float4* src = (const float4*)(nodes + gnext * 4 * 2112);
#pragma unroll
            for (int qq = 0; qq < 9; ++qq)
                if (sq[qq] < 2112) {
                    unsigned dst = (unsigned)__cvta_generic_to_shared(
                        &sN[sb_[qq]][sr[qq] * RS + si[qq] * 4]);
                    CP_ASYNC16(dst, src + sq[qq]);
                }
        }
        asm volatile("cp.async.commit_group;" ::: "memory");
        float ek_next = 0.f;
        if (half == 0 && gnext < NGRP) {
            const float4* er = (const float4*)(edges + ((gnext * 4 + bl) * 32 + lane) * 16);
#pragma unroll
            for (int e4 = 0; e4 < 4; ++e4) {
                float4 a = er[e4];
                ek_next += a.x * ewp[e4 * 4] + a.y * ewp[e4 * 4 + 1]
                         + a.z * ewp[e4 * 4 + 2] + a.w * ewp[e4 * 4 + 3];
            }
        }

        // ---- add bias; per-row stats (sum, sumsq, score) ----
#pragma unroll
        for (int m = 0; m < 3; ++m)
#pragma unroll
            for (int j = 0; j < 4; ++j) {
                d[m][j][0] += wb2[j].x; d[m][j][1] += wb2[j].y;
                d[m][j][2] += wb2[j].x; d[m][j][3] += wb2[j].y;
            }

        float sm[3][2], s2[3][2], sc[3][2];
#pragma unroll
        for (int m = 0; m < 3; ++m)
#pragma unroll
            for (int rh = 0; rh < 2; ++rh) {
                float a = 0.f, q = 0.f, s = 0.f;
#pragma unroll
                for (int j = 0; j < 4; ++j) {
                    float h0 = d[m][j][rh * 2], h1 = d[m][j][rh * 2 + 1];
                    a += h0 + h1;
                    q = fmaf(h0, h0, fmaf(h1, h1, q));
                    s = fmaf(h0, aw2[j].x, fmaf(h1, aw2[j].y, s));
                }
#pragma unroll
                for (int dl = 1; dl <= 2; dl <<= 1) {
                    a += __shfl_xor_sync(0xffffffffu, a, dl);
                    q += __shfl_xor_sync(0xffffffffu, q, dl);
                    s += __shfl_xor_sync(0xffffffffu, s, dl);
                }
                sm[m][rh] = a; s2[m][rh] = q; sc[m][rh] = s;
            }
        if (t == 0) {
            sSum[bl][half][g]      = make_float2(sm[0][0], s2[0][0]);
            sSum[bl][half][g + 8]  = make_float2(sm[0][1], s2[0][1]);
            sSum[bl][half][g + 16] = make_float2(sm[1][0], s2[1][0]);
            sSum[bl][half][g + 24] = make_float2(sm[1][1], s2[1][1]);
            if (g > 0) sScore[bl][half][g - 1] = sc[0][0];
            sScore[bl][half][g + 7]  = sc[0][1];   // row g+8
            sScore[bl][half][g + 15] = sc[1][0];   // row 16+g
            sScore[bl][half][g + 23] = sc[1][1];   // row 24+g
            if (g == 0) {
                sSum[bl][half][32]   = make_float2(sm[2][0], s2[2][0]);
                sScore[bl][half][31] = sc[2][0];   // row 32
            }
        }
        BARX(barid);   // only this batch's 2 warps

        // ---- layernorm + store for neighbor rows (1..32) ----
        float* gO = out + b * 2112;
#pragma unroll
        for (int m = 0; m < 3; ++m)
#pragma unroll
            for (int rh = 0; rh < 2; ++rh) {
                int row = m * 16 + g + rh * 8;
                bool valid = (row >= 1) && (row <= 32) && !(m == 2 && !(g == 0 && rh == 0));
                if (valid) {
                    float2 u0 = sSum[bl][0][row];
                    float2 u1 = sSum[bl][1][row];
                    float mu  = (u0.x + u1.x) * (1.f / 64.f);
                    float var = fmaf(u0.y + u1.y, 1.f / 64.f, -mu * mu);
                    float ri  = rsqrtf(var + EPSLN);
#pragma unroll
                    for (int j = 0; j < 4; ++j) {
                        float2 o;
                        o.x = fmaf((d[m][j][rh * 2]     - mu) * ri, g2[j].x, be2[j].x);
                        o.y = fmaf((d[m][j][rh * 2 + 1] - mu) * ri, g2[j].y, be2[j].y);
                        *(float2*)(gO + row * 64 + col0 + j * 8) = o;
                    }
                }
            }

        // ---- softmax over 32 neighbor scores (half==0 warp of each batch) ----
        if (half == 0) {
            float s = sScore[bl][0][lane] + sScore[bl][1][lane] + ek_cur;
            float mx = s;
#pragma unroll
            for (int dl = 16; dl > 0; dl >>= 1) mx = fmaxf(mx, __shfl_xor_sync(0xffffffffu, mx, dl));
            float p = __expf(s - mx);
            float tot = p;
#pragma unroll
            for (int dl = 16; dl > 0; dl >>= 1) tot += __shfl_xor_sync(0xffffffffu, tot, dl);
            sAttn[bl][lane] = p / tot;
        }
        BARX(barid);

        // ---- messages: msg[col] = sum_k attn_k * h_k[col] ----
        float aA = (g > 0) ? sAttn[bl][g - 1] : 0.f;   // row g
        float aB = sAttn[bl][g + 7];                    // row g+8
        float aC = sAttn[bl][g + 15];                   // row 16+g
        float aD = sAttn[bl][g + 23];                   // row 24+g
        float aE = (g == 0) ? sAttn[bl][31] : 0.f;      // row 32

        float pm[4][2];
#pragma unroll
        for (int j = 0; j < 4; ++j)
#pragma unroll
            for (int c = 0; c < 2; ++c) {
                float v = aA * d[0][j][c] + aB * d[0][j][2 + c]
                        + aC * d[1][j][c] + aD * d[1][j][2 + c]
                        + aE * d[2][j][c];
#pragma unroll
                for (int dl = 4; dl <= 16; dl <<= 1)
                    v += __shfl_xor_sync(0xffffffffu, v, dl);
                pm[j][c] = v;
            }

        // ---- target row 0 (held by g==0 lanes) ----
        float tv[4][2];
        float tsm = 0.f, ts2 = 0.f;
#pragma unroll
        for (int j = 0; j < 4; ++j)
#pragma unroll
            for (int c = 0; c < 2; ++c) {
                float v = d[0][j][c] + pm[j][c];
                tv[j][c] = v;
                tsm += v;
                ts2 = fmaf(v, v, ts2);
            }
#pragma unroll
        for (int dl = 1; dl <= 2; dl <<= 1) {
            tsm += __shfl_xor_sync(0xffffffffu, tsm, dl);
            ts2 += __shfl_xor_sync(0xffffffffu, ts2, dl);
        }
        if (lane == 0) sT[bl][half] = make_float2(tsm, ts2);
        BARX(barid);

        if (lane < 4) {  // g==0, t=0..3 lanes write target row
            float2 v0 = sT[bl][0], v1 = sT[bl][1];
            float mu  = (v0.x + v1.x) * (1.f / 64.f);
            float var = fmaf(v0.y + v1.y, 1.f / 64.f, -mu * mu);
            float ri  = rsqrtf(var + EPSLN);
#pragma unroll
            for (int j = 0; j < 4; ++j) {
                float2 o;
                o.x = fmaf((tv[j][0] - mu) * ri, g2[j].x, be2[j].x);
                o.y = fmaf((tv[j][1] - mu) * ri, g2[j].y, be2[j].y);
                *(float2*)(gO + col0 + j * 8) = o;
            }
        }

        ek_cur = ek_next;
        asm volatile("cp.async.wait_group 0;" ::: "memory");
        __syncthreads();   // next group's nodes visible to all warps
    }
}

extern "C" void kernel_launch(void* const* d_in, const int* in_sizes, int n_in,
                              void* d_out, int out_size) {
    const float* nodes = (const float*)d_in[0];
    const float* edges = (const float*)d_in[1];
    const float* Ww    = (const float*)d_in[2];
    const float* Wb    = (const float*)d_in[3];
    const float* Wew   = (const float*)d_in[4];
    // d_in[5] = We_b   (cancels under softmax shift-invariance)
    const float* attw  = (const float*)d_in[6];
    // d_in[7] = attn_b (cancels under softmax shift-invariance)
    const float* gamma = (const float*)d_in[8];
    const float* beta  = (const float*)d_in[9];

    prep_kernel<<<16, 128>>>(Ww, Wew, attw);
    gat_kernel<<<GRID, 256>>>(nodes, edges, Wb, attw, gamma, beta, (float*)d_out);
}